// round 14
// baseline (speedup 1.0000x reference)
#include <cuda_runtime.h>

#define BB 4
#define NN 128
#define DD 128
#define EPS 1e-6f

// scratch for x = dense2(glu(dense1(rmsnorm(q))))  : (B, N, 3D) floats
__device__ float g_x[BB * NN * 3 * DD];

// ---------------------------------------------------------------------------
// Phase A: per-row RMSNorm -> GEMM1 (D->2D) -> GLU -> GEMM2 (D->3D) -> g_x
// Also initializes out with q / mu (phaseB accumulates into out atomically).
// 4 rows per block, 256 threads, thread-per-output GEMV. Grid = 128 blocks.
// (Empirically the fastest phaseA variant across rounds 3-10.)
// ---------------------------------------------------------------------------
__global__ __launch_bounds__(256) void phaseA_kernel(
    const float* __restrict__ q,
    const float* __restrict__ mu,
    const float* __restrict__ norm_w,
    const float* __restrict__ W1,
    const float* __restrict__ b1,
    const float* __restrict__ W2,
    const float* __restrict__ b2,
    float* __restrict__ out)
{
    __shared__ float hs[4][DD];     // normed input
    __shared__ float ys[4][2 * DD]; // GEMM1 output
    __shared__ float h2s[4][DD];    // GLU output
    __shared__ float rms[4];

    const int tid = threadIdx.x;
    const int row0 = blockIdx.x * 4;   // global row = b*N + n

    // init out with q and mu (phaseB adds dq/dmu via atomics)
    {
        const float4* qs = (const float4*)(q) + row0 * (DD / 4);
        float4* oq = (float4*)(out) + row0 * (DD / 4);
        for (int c = tid; c < 4 * (DD / 4); c += 256) oq[c] = qs[c];
        const float4* ms = (const float4*)(mu) + row0 * (3 * DD / 4);
        float4* om = (float4*)(out + BB * NN * DD) + row0 * (3 * DD / 4);
        for (int c = tid; c < 4 * (3 * DD / 4); c += 256) om[c] = ms[c];
    }

    // load q rows into smem
    if (tid < DD) {
        #pragma unroll
        for (int r = 0; r < 4; r++)
            hs[r][tid] = q[(row0 + r) * DD + tid];
    }
    __syncthreads();

    // per-row sum of squares (warp r reduces row r)
    const int w = tid >> 5, l = tid & 31;
    if (w < 4) {
        float s = 0.f;
        #pragma unroll
        for (int c = l; c < DD; c += 32) { float v = hs[w][c]; s += v * v; }
        #pragma unroll
        for (int o = 16; o; o >>= 1) s += __shfl_xor_sync(0xffffffffu, s, o);
        if (l == 0) rms[w] = rsqrtf(s * (1.0f / DD) + EPS);
    }
    __syncthreads();

    if (tid < DD) {
        const float nw = 1.0f + norm_w[tid];
        #pragma unroll
        for (int r = 0; r < 4; r++)
            hs[r][tid] *= rms[r] * nw;
    }
    __syncthreads();

    // GEMM1: y[r][o] = b1[o] + sum_d hs[r][d] * W1[o][d]   (o = tid in [0,256))
    {
        const int o = tid;
        float a0 = b1[o], a1 = a0, a2 = a0, a3 = a0;
        const float4* wrow = (const float4*)(W1) + o * (DD / 4);
        const float4* h0 = (const float4*)hs[0];
        const float4* h1 = (const float4*)hs[1];
        const float4* h2 = (const float4*)hs[2];
        const float4* h3 = (const float4*)hs[3];
        #pragma unroll
        for (int d4 = 0; d4 < DD / 4; d4++) {
            float4 wv = __ldg(wrow + d4);
            float4 v;
            v = h0[d4]; a0 += wv.x*v.x + wv.y*v.y + wv.z*v.z + wv.w*v.w;
            v = h1[d4]; a1 += wv.x*v.x + wv.y*v.y + wv.z*v.z + wv.w*v.w;
            v = h2[d4]; a2 += wv.x*v.x + wv.y*v.y + wv.z*v.z + wv.w*v.w;
            v = h3[d4]; a3 += wv.x*v.x + wv.y*v.y + wv.z*v.z + wv.w*v.w;
        }
        ys[0][o] = a0; ys[1][o] = a1; ys[2][o] = a2; ys[3][o] = a3;
    }
    __syncthreads();

    // GLU: h2 = silu(a) * sigmoid(g)
    if (tid < DD) {
        #pragma unroll
        for (int r = 0; r < 4; r++) {
            float a = ys[r][tid];
            float g = ys[r][tid + DD];
            float sa = 1.0f / (1.0f + __expf(-a));
            float sg = 1.0f / (1.0f + __expf(-g));
            h2s[r][tid] = a * sa * sg;
        }
    }
    __syncthreads();

    // GEMM2: x[r][c] = b2[c] + sum_d h2s[r][d] * W2[c][d], c in [0,384)
    for (int c = tid; c < 3 * DD; c += 256) {
        float a0 = b2[c], a1 = a0, a2 = a0, a3 = a0;
        const float4* wrow = (const float4*)(W2) + c * (DD / 4);
        const float4* h0 = (const float4*)h2s[0];
        const float4* h1 = (const float4*)h2s[1];
        const float4* h2 = (const float4*)h2s[2];
        const float4* h3 = (const float4*)h2s[3];
        #pragma unroll
        for (int d4 = 0; d4 < DD / 4; d4++) {
            float4 wv = __ldg(wrow + d4);
            float4 v;
            v = h0[d4]; a0 += wv.x*v.x + wv.y*v.y + wv.z*v.z + wv.w*v.w;
            v = h1[d4]; a1 += wv.x*v.x + wv.y*v.y + wv.z*v.z + wv.w*v.w;
            v = h2[d4]; a2 += wv.x*v.x + wv.y*v.y + wv.z*v.z + wv.w*v.w;
            v = h3[d4]; a3 += wv.x*v.x + wv.y*v.y + wv.z*v.z + wv.w*v.w;
        }
        g_x[(row0 + 0) * 3 * DD + c] = a0;
        g_x[(row0 + 1) * 3 * DD + c] = a1;
        g_x[(row0 + 2) * 3 * DD + c] = a2;
        g_x[(row0 + 3) * 3 * DD + c] = a3;
    }
}

// ---------------------------------------------------------------------------
// Phase B: pairwise accumulation, 5-stage cp.async ring, 1 j per stage.
// Block = (b, 4-i tile, 32-j tile). Grid = 512, 256 threads = 8 warps:
//   warp w: il = w & 3 (row), h = w >> 2 (channel half: 64 channels).
//   lane l owns channels [h*64 + 2l, h*64 + 2l + 1] (float2 granularity).
// Decode puts it in the low bits so co-scheduled blocks share the x/mu
// j-range (L2 locality) while spreading atomic targets.
// Ring safety: issue(s+4) at end of iter s overwrites slot (s+4)%5 =
// (s-1)%5; every warp finished consuming stage s-1 before the barrier of
// iteration s, which precedes the issue.
// ---------------------------------------------------------------------------
#define SJ_F4 576
#define SJ_BYTES 9216
#define NSTG 5

__device__ __forceinline__ void cp16(unsigned int dst, const void* src) {
    asm volatile("cp.async.cg.shared.global [%0], [%1], 16;" :: "r"(dst), "l"(src));
}

__global__ __launch_bounds__(256, 4) void phaseB_kernel(
    const float* __restrict__ mu,
    const float* __restrict__ Wij,
    const float* __restrict__ dir_ij,
    const float* __restrict__ mask_ij,
    float* __restrict__ out)
{
    __shared__ float4 sStage[NSTG][SJ_F4];   // 46080 B
    __shared__ float smsk[4][32];            // 512 B
    __shared__ float sdir[4][32][3];         // 1536 B

    const int tid = threadIdx.x;
    const int w = tid >> 5, l = tid & 31;
    const int it = blockIdx.x & 31;
    const int b  = (blockIdx.x >> 5) & 3;
    const int jt = blockIdx.x >> 7;
    const int i0 = it * 4;
    const int il = w & 3;
    const int h  = w >> 2;
    const int jb0 = jt * 32;

    // --- stage mask / dir into smem (visible after first barrier) ---
    if (tid < 128) {
        int mil = tid >> 5, jl = tid & 31;
        smsk[mil][jl] = __ldg(mask_ij + (b * NN + i0 + mil) * NN + jb0 + jl);
    }
    for (int e = tid; e < 384; e += 256) {
        int mil = e / 96, r = e % 96;
        int jl = r / 3, k = r % 3;
        sdir[mil][jl][k] = __ldg(dir_ij + ((b * NN + i0 + mil) * NN + jb0 + jl) * 3 + k);
    }

    // --- per-thread cp.async slots (all sources advance by 96 f4 per j) ---
    const float4* Wf4  = (const float4*)Wij;
    const float4* xf4  = (const float4*)g_x;
    const float4* muf4 = (const float4*)mu;
    const float4* slotSrc[3];
    unsigned int slotDst[3];
    unsigned int sbase = (unsigned int)__cvta_generic_to_shared(&sStage[0][0]);
    #pragma unroll
    for (int k = 0; k < 3; k++) {
        int e = tid + k * 256;
        const float4* src = 0;
        if (e < SJ_F4) {
            if (e < 384) {
                src = Wf4 + ((size_t)(b * NN + i0 + e / 96) * NN + jb0) * 96 + (e % 96);
            } else if (e < 480) {
                src = xf4 + (size_t)(b * NN + jb0) * 96 + (e - 384);
            } else {
                src = muf4 + (size_t)(b * NN + jb0) * 96 + (e - 480);
            }
        }
        slotSrc[k] = src;
        slotDst[k] = sbase + (unsigned int)e * 16u;
    }
    const bool slot2 = (tid < 64);

#define ISSUE_STAGE(s)                                                   \
    {                                                                    \
        const unsigned int bo = ((s) % NSTG) * (unsigned int)SJ_BYTES;   \
        const int adv = (s) * 96;                                        \
        cp16(slotDst[0] + bo, slotSrc[0] + adv);                         \
        cp16(slotDst[1] + bo, slotSrc[1] + adv);                         \
        if (slot2) cp16(slotDst[2] + bo, slotSrc[2] + adv);              \
        asm volatile("cp.async.commit_group;" ::: "memory");             \
    }

    ISSUE_STAGE(0)
    ISSUE_STAGE(1)
    ISSUE_STAGE(2)
    ISSUE_STAGE(3)

    float2 accq = make_float2(0.f, 0.f);
    float2 am0 = accq, am1 = accq, am2 = accq;

    const int co = h * 32 + l;   // float2 index within a 64-f2 segment

    for (int s = 0; s < 32; s++) {
        if (s <= 28)      asm volatile("cp.async.wait_group 3;" ::: "memory");
        else if (s == 29) asm volatile("cp.async.wait_group 2;" ::: "memory");
        else if (s == 30) asm volatile("cp.async.wait_group 1;" ::: "memory");
        else              asm volatile("cp.async.wait_group 0;" ::: "memory");
        __syncthreads();

        const float2* stg2 = (const float2*)&sStage[s % NSTG][0];
        const float m  = smsk[il][s];
        const float d0 = sdir[il][s][0];
        const float d1 = sdir[il][s][1];
        const float d2 = sdir[il][s][2];

        float2 wq = stg2[il * 192 + co];
        float2 wr = stg2[il * 192 + 64 + co];
        float2 wm = stg2[il * 192 + 128 + co];
        float2 xq = stg2[768 + co];
        float2 xr = stg2[832 + co];
        float2 xm = stg2[896 + co];
        float2 m0 = stg2[960 + co];
        float2 m1 = stg2[1024 + co];
        float2 m2 = stg2[1088 + co];

#define PAINN_COMP(c)                                                   \
        {                                                               \
            accq.c = fmaf(wq.c * xq.c, m, accq.c);                      \
            float t = wr.c * xr.c * m;                                  \
            am0.c = fmaf(t, d0, am0.c);                                 \
            am1.c = fmaf(t, d1, am1.c);                                 \
            am2.c = fmaf(t, d2, am2.c);                                 \
            t = wm.c * xm.c * m;                                        \
            am0.c = fmaf(t, m0.c, am0.c);                               \
            am1.c = fmaf(t, m1.c, am1.c);                               \
            am2.c = fmaf(t, m2.c, am2.c);                               \
        }
        PAINN_COMP(x)
        PAINN_COMP(y)
#undef PAINN_COMP

        if (s < 28) ISSUE_STAGE(s + 4)
    }
#undef ISSUE_STAGE

    // --- direct atomic epilogue: warp owns disjoint (i, channel pair) ---
    const int bio = b * NN + i0 + il;
    const int c0 = 2 * co;                 // first of 2 channels
    float* oq = out + bio * DD + c0;
    atomicAdd(oq + 0, accq.x);
    atomicAdd(oq + 1, accq.y);
    float* om = out + BB * NN * DD + bio * 3 * DD + c0;
    atomicAdd(om + 0,          am0.x);
    atomicAdd(om + 1,          am0.y);
    atomicAdd(om + DD + 0,     am1.x);
    atomicAdd(om + DD + 1,     am1.y);
    atomicAdd(om + 2 * DD + 0, am2.x);
    atomicAdd(om + 2 * DD + 1, am2.y);
}

// ---------------------------------------------------------------------------
extern "C" void kernel_launch(void* const* d_in, const int* in_sizes, int n_in,
                              void* d_out, int out_size)
{
    const float* q       = (const float*)d_in[0];
    const float* mu      = (const float*)d_in[1];
    const float* Wij     = (const float*)d_in[2];
    const float* dir_ij  = (const float*)d_in[3];
    const float* mask_ij = (const float*)d_in[4];
    const float* norm_w  = (const float*)d_in[5];
    const float* W1      = (const float*)d_in[6];
    const float* b1      = (const float*)d_in[7];
    const float* W2      = (const float*)d_in[8];
    const float* b2      = (const float*)d_in[9];
    float* out = (float*)d_out;

    phaseA_kernel<<<(BB * NN) / 4, 256>>>(q, mu, norm_w, W1, b1, W2, b2, out);
    phaseB_kernel<<<BB * NN, 256>>>(mu, Wij, dir_ij, mask_ij, out);
}